// round 13
// baseline (speedup 1.0000x reference)
#include <cuda_runtime.h>
#include <math.h>

#define C_IN  64
#define C_HID 64
#define C_OUT 40
#define NMAX  50000
#define EMAX  800000

// Scratch (allocation-free rule). 16B aligned for float4 ops on MY buffers.
__device__ __align__(16) float g_h1[NMAX * C_HID];   // x @ W1 (UNSCALED)
__device__ __align__(16) float g_feat[NMAX * C_HID]; // layer-1 output (post relu)
__device__ __align__(16) float g_h2s[NMAX * C_OUT];  // (feat @ W2) * dinv[row]
__device__ int   g_deg[NMAX];     // zeroed by alloc_kernel after use
__device__ float g_dinv[NMAX];
__device__ int   g_start[NMAX];   // CSR range base per dst (unordered bases)
__device__ int   g_cursor[NMAX];  // placement cursor; == range END after fill
__device__ int   g_csr[EMAX];     // src ids grouped by dst
__device__ int   g_total;         // ticket counter; reset by agg2

// ---------------------------------------------------------------------------
// Shared GEMM tile body (R7-proven): thread-per-output-column, 64-row tiles.
// ---------------------------------------------------------------------------
template <int CIN, int COUT, bool SCALE>
__device__ __forceinline__ void gemm_tile(const float* __restrict__ Xin,
                                          const float* __restrict__ W,
                                          float* __restrict__ H,
                                          int N, int row0) {
    constexpr int ROWS = 64;
    __shared__ float Ws[CIN * COUT];
    __shared__ float Xs[ROWS * CIN];

    int tid  = threadIdx.y * blockDim.x + threadIdx.x;
    int nthr = blockDim.x * blockDim.y;

    for (int i = tid; i < CIN * COUT; i += nthr) Ws[i] = W[i];

    int nrows = min(ROWS, N - row0);
    for (int i = tid; i < nrows * CIN; i += nthr) Xs[i] = Xin[(size_t)row0 * CIN + i];
    __syncthreads();

    int c = threadIdx.x;
    for (int r = threadIdx.y; r < nrows; r += blockDim.y) {
        float acc = 0.f;
#pragma unroll
        for (int k = 0; k < CIN; k++) acc += Xs[r * CIN + k] * Ws[k * COUT + c];
        float o = acc;
        if (SCALE) o *= g_dinv[row0 + r];
        H[(size_t)(row0 + r) * COUT + c] = o;
    }
}

// ---------------------------------------------------------------------------
// Fused A: first half of gemm1 (unscaled) || degree histogram (4 edges/thread
// via int4 loads for MLP). (proven R12)
// ---------------------------------------------------------------------------
__global__ void __launch_bounds__(256)
fusedA_kernel(const float* __restrict__ x, const float* __restrict__ W1,
              const int* __restrict__ ei, int E, int N, int GA, int DB) {
    if ((int)blockIdx.x < GA) {
        gemm_tile<C_IN, C_HID, false>(x, W1, g_h1, N, blockIdx.x * 64);
    } else {
        int tid = threadIdx.y * blockDim.x + threadIdx.x;
        int bid = (int)blockIdx.x - GA;
        const int4* d4 = (const int4*)(ei + E);
        int nq = E >> 2;
        for (int q = bid * 256 + tid; q < nq; q += DB * 256) {
            int4 d = d4[q];
            atomicAdd(&g_deg[d.x], 1);
            atomicAdd(&g_deg[d.y], 1);
            atomicAdd(&g_deg[d.z], 1);
            atomicAdd(&g_deg[d.w], 1);
        }
        for (int e = (nq << 2) + bid * 256 + tid; e < E; e += DB * 256)
            atomicAdd(&g_deg[ei[E + e]], 1);
    }
}

// ---------------------------------------------------------------------------
// Scan-free CSR range allocation (proven R10/R12).
// ---------------------------------------------------------------------------
__global__ void __launch_bounds__(256)
alloc_kernel(int N) {
    __shared__ int warp_sums[8];
    __shared__ int s_base;
    int t    = threadIdx.x;
    int lane = t & 31;
    int wid  = t >> 5;
    int i0   = blockIdx.x * 512 + 2 * t;

    int a = (i0 < N)     ? g_deg[i0]     : 0;
    int b = (i0 + 1 < N) ? g_deg[i0 + 1] : 0;
    int pair = a + b;

    int v = pair;
#pragma unroll
    for (int o = 1; o < 32; o <<= 1) {
        int u = __shfl_up_sync(0xFFFFFFFFu, v, o);
        if (lane >= o) v += u;
    }
    if (lane == 31) warp_sums[wid] = v;
    __syncthreads();
    if (wid == 0) {
        int w = (lane < 8) ? warp_sums[lane] : 0;
#pragma unroll
        for (int o = 1; o < 32; o <<= 1) {
            int u = __shfl_up_sync(0xFFFFFFFFu, w, o);
            if (lane >= o) w += u;
        }
        if (lane < 8) warp_sums[lane] = w;
    }
    __syncthreads();
    int carry = (wid > 0) ? warp_sums[wid - 1] : 0;
    int incl  = v + carry;
    if (t == 255) s_base = atomicAdd(&g_total, incl);
    __syncthreads();
    int excl = incl - pair + s_base;
    if (i0 < N) {
        g_start[i0]  = excl;
        g_cursor[i0] = excl;
        g_dinv[i0]   = rsqrtf((float)(a + 1));
        g_deg[i0]    = 0;
    }
    if (i0 + 1 < N) {
        g_start[i0 + 1]  = excl + a;
        g_cursor[i0 + 1] = excl + a;
        g_dinv[i0 + 1]   = rsqrtf((float)(b + 1));
        g_deg[i0 + 1]    = 0;
    }
}

// ---------------------------------------------------------------------------
// Fused B: second half of gemm1 (unscaled) || CSR fill (4 edges/thread).
// (proven R12)
// ---------------------------------------------------------------------------
__global__ void __launch_bounds__(256)
fusedB_kernel(const float* __restrict__ x, const float* __restrict__ W1,
              const int* __restrict__ ei, int E, int N, int GA, int GB, int FB) {
    if ((int)blockIdx.x < GB) {
        gemm_tile<C_IN, C_HID, false>(x, W1, g_h1, N, (GA + blockIdx.x) * 64);
    } else {
        int tid = threadIdx.y * blockDim.x + threadIdx.x;
        int bid = (int)blockIdx.x - GB;
        const int4* s4 = (const int4*)ei;
        const int4* d4 = (const int4*)(ei + E);
        int nq = E >> 2;
        for (int q = bid * 256 + tid; q < nq; q += FB * 256) {
            int4 s = s4[q];
            int4 d = d4[q];
            g_csr[atomicAdd(&g_cursor[d.x], 1)] = s.x;
            g_csr[atomicAdd(&g_cursor[d.y], 1)] = s.y;
            g_csr[atomicAdd(&g_cursor[d.z], 1)] = s.z;
            g_csr[atomicAdd(&g_cursor[d.w], 1)] = s.w;
        }
        for (int e = (nq << 2) + bid * 256 + tid; e < E; e += FB * 256) {
            int s = ei[e];
            int d = ei[E + e];
            g_csr[atomicAdd(&g_cursor[d], 1)] = s;
        }
    }
}

// ---------------------------------------------------------------------------
// Layer-1 aggregate (standalone again for occupancy):
//   feat[d] = relu(dinv[d]*(dinv[d]*h1[d] + sum_s dinv[s]*h1[s]) + b1)
// Half-warp per node; degree loop 4-way index-batched for MLP.
// ---------------------------------------------------------------------------
__global__ void __launch_bounds__(256)
agg1_kernel(const float* __restrict__ b1, int N) {
    int lane = threadIdx.x & 31;
    int warp = (blockIdx.x * blockDim.x + threadIdx.x) >> 5;
    int node = warp * 2 + (lane >> 4);
    if (node >= N) return;
    int sub = lane & 15;

    const float4* hs = (const float4*)g_h1;
    float dn = g_dinv[node];

    float4 self = hs[node * 16 + sub];
    float4 acc;
    acc.x = self.x * dn; acc.y = self.y * dn;
    acc.z = self.z * dn; acc.w = self.w * dn;

    int i = g_start[node], end = g_cursor[node];
    for (; i + 4 <= end; i += 4) {
        int s0 = g_csr[i], s1 = g_csr[i + 1], s2 = g_csr[i + 2], s3 = g_csr[i + 3];
        float d0 = g_dinv[s0], d1 = g_dinv[s1], d2 = g_dinv[s2], d3 = g_dinv[s3];
        float4 a0 = hs[s0 * 16 + sub];
        float4 a1 = hs[s1 * 16 + sub];
        float4 a2 = hs[s2 * 16 + sub];
        float4 a3 = hs[s3 * 16 + sub];
        acc.x = fmaf(a0.x, d0, fmaf(a1.x, d1, fmaf(a2.x, d2, fmaf(a3.x, d3, acc.x))));
        acc.y = fmaf(a0.y, d0, fmaf(a1.y, d1, fmaf(a2.y, d2, fmaf(a3.y, d3, acc.y))));
        acc.z = fmaf(a0.z, d0, fmaf(a1.z, d1, fmaf(a2.z, d2, fmaf(a3.z, d3, acc.z))));
        acc.w = fmaf(a0.w, d0, fmaf(a1.w, d1, fmaf(a2.w, d2, fmaf(a3.w, d3, acc.w))));
    }
    for (; i < end; i++) {
        int s = g_csr[i];
        float ds = g_dinv[s];
        float4 a = hs[s * 16 + sub];
        acc.x = fmaf(a.x, ds, acc.x);
        acc.y = fmaf(a.y, ds, acc.y);
        acc.z = fmaf(a.z, ds, acc.z);
        acc.w = fmaf(a.w, ds, acc.w);
    }
    int c = sub * 4;
    float4 o;
    o.x = fmaxf(fmaf(acc.x, dn, b1[c + 0]), 0.f);
    o.y = fmaxf(fmaf(acc.y, dn, b1[c + 1]), 0.f);
    o.z = fmaxf(fmaf(acc.z, dn, b1[c + 2]), 0.f);
    o.w = fmaxf(fmaf(acc.w, dn, b1[c + 3]), 0.f);
    ((float4*)g_feat)[node * 16 + sub] = o;
}

// ---------------------------------------------------------------------------
// Layer 2 GEMM: h2s[r,:] = (feat[r,:] @ W2) * dinv[r].
// ---------------------------------------------------------------------------
__global__ void gemm2_kernel(const float* __restrict__ W, int N) {
    gemm_tile<C_HID, C_OUT, true>(g_feat, W, g_h2s, N, blockIdx.x * 64);
}

// ---------------------------------------------------------------------------
// Layer-2 aggregate + bias + log_softmax (h2s pre-scaled by dinv[src]).
// Resets g_total for the next invocation.
// ---------------------------------------------------------------------------
__global__ void agg2_kernel(const float* __restrict__ b2,
                            float* __restrict__ out, int N) {
    if (blockIdx.x == 0 && threadIdx.x == 0) g_total = 0;

    int lane = threadIdx.x & 31;
    int warp = (blockIdx.x * blockDim.x + threadIdx.x) >> 5;
    int node = warp * 2 + (lane >> 4);
    int sub  = lane & 15;
    bool valid = (node < N) && (sub < 10);
    int nc = (node < N) ? node : 0;

    float4 v = make_float4(-INFINITY, -INFINITY, -INFINITY, -INFINITY);
    if (valid) {
        const float4* hs = (const float4*)g_h2s;
        float4 acc = hs[nc * 10 + sub];  // self loop
        int i = g_start[nc], end = g_cursor[nc];
        for (; i + 4 <= end; i += 4) {
            int s0 = g_csr[i], s1 = g_csr[i + 1], s2 = g_csr[i + 2], s3 = g_csr[i + 3];
            float4 a0 = hs[s0 * 10 + sub];
            float4 a1 = hs[s1 * 10 + sub];
            float4 a2 = hs[s2 * 10 + sub];
            float4 a3 = hs[s3 * 10 + sub];
            acc.x += (a0.x + a1.x) + (a2.x + a3.x);
            acc.y += (a0.y + a1.y) + (a2.y + a3.y);
            acc.z += (a0.z + a1.z) + (a2.z + a3.z);
            acc.w += (a0.w + a1.w) + (a2.w + a3.w);
        }
        for (; i < end; i++) {
            float4 a = hs[g_csr[i] * 10 + sub];
            acc.x += a.x; acc.y += a.y; acc.z += a.z; acc.w += a.w;
        }
        float di = g_dinv[nc];
        int c = sub * 4;
        v = make_float4(fmaf(acc.x, di, b2[c + 0]),
                        fmaf(acc.y, di, b2[c + 1]),
                        fmaf(acc.z, di, b2[c + 2]),
                        fmaf(acc.w, di, b2[c + 3]));
    }

    float m = fmaxf(fmaxf(v.x, v.y), fmaxf(v.z, v.w));
#pragma unroll
    for (int o = 8; o; o >>= 1) m = fmaxf(m, __shfl_xor_sync(0xFFFFFFFFu, m, o));

    float s = valid ? (expf(v.x - m) + expf(v.y - m) + expf(v.z - m) + expf(v.w - m))
                    : 0.f;
#pragma unroll
    for (int o = 8; o; o >>= 1) s += __shfl_xor_sync(0xFFFFFFFFu, s, o);

    float lg = m + logf(s);
    if (valid) {
        float4 o4 = make_float4(v.x - lg, v.y - lg, v.z - lg, v.w - lg);
        ((float4*)out)[nc * 10 + sub] = o4;
    }
}

// ---------------------------------------------------------------------------
extern "C" void kernel_launch(void* const* d_in, const int* in_sizes, int n_in,
                              void* d_out, int out_size) {
    const float* x  = (const float*)d_in[0];
    const int*   ei = (const int*)d_in[1];
    const float* W1 = (const float*)d_in[2];
    const float* b1 = (const float*)d_in[3];
    const float* W2 = (const float*)d_in[4];
    const float* b2 = (const float*)d_in[5];
    float* out = (float*)d_out;

    int N = in_sizes[0] / C_IN;
    int E = in_sizes[1] / 2;

    int G  = (N + 63) / 64;   // gemm tiles
    int GA = (G + 1) / 2;
    int GB = G - GA;
    int DB = 512;             // deg partner blocks
    int FB = 512;             // fill partner blocks

    fusedA_kernel<<<GA + DB, dim3(64, 4)>>>(x, W1, ei, E, N, GA, DB);
    alloc_kernel<<<(N + 511) / 512, 256>>>(N);
    fusedB_kernel<<<GB + FB, dim3(64, 4)>>>(x, W1, ei, E, N, GA, GB, FB);
    agg1_kernel<<<(N + 15) / 16, 256>>>(b1, N);
    gemm2_kernel<<<G, dim3(C_OUT, 6)>>>(W2, N);
    agg2_kernel<<<(N + 15) / 16, 256>>>(b2, out, N);
}

// round 14
// speedup vs baseline: 1.0678x; 1.0678x over previous
#include <cuda_runtime.h>
#include <cuda_fp16.h>
#include <math.h>

#define C_IN  64
#define C_HID 64
#define C_OUT 40
#define NMAX  50000
#define EMAX  800000

// Scratch (allocation-free rule). 16B aligned for vector ops on MY buffers.
__device__ __align__(16) __half g_h1h[NMAX * C_HID];  // x @ W1 (UNSCALED, fp16)
__device__ __align__(16) float  g_feat[NMAX * C_HID]; // layer-1 output (fp32)
__device__ __align__(16) __half g_h2h[NMAX * C_OUT];  // (feat @ W2)*dinv (fp16)
__device__ int   g_deg[NMAX];     // zeroed by alloc_kernel after use
__device__ float g_dinv[NMAX];
__device__ int   g_start[NMAX];   // CSR range base per dst (unordered bases)
__device__ int   g_cursor[NMAX];  // placement cursor; == range END after fill
__device__ int   g_csr[EMAX];     // src ids grouped by dst
__device__ int   g_total;         // ticket counter; reset by agg2

// Unpack 4 halves (uint2) -> float4
__device__ __forceinline__ float4 h4_to_f4(uint2 u) {
    __half2 h0 = *reinterpret_cast<__half2*>(&u.x);
    __half2 h1 = *reinterpret_cast<__half2*>(&u.y);
    float2 f0 = __half22float2(h0);
    float2 f1 = __half22float2(h1);
    return make_float4(f0.x, f0.y, f1.x, f1.y);
}

// ---------------------------------------------------------------------------
// Shared GEMM tile body (R7-proven): thread-per-output-column, 64-row tiles.
// Stores fp16; optional dinv scale.
// ---------------------------------------------------------------------------
template <int CIN, int COUT, bool SCALE>
__device__ __forceinline__ void gemm_tile(const float* __restrict__ Xin,
                                          const float* __restrict__ W,
                                          __half* __restrict__ H,
                                          int N, int row0) {
    constexpr int ROWS = 64;
    __shared__ float Ws[CIN * COUT];
    __shared__ float Xs[ROWS * CIN];

    int tid  = threadIdx.y * blockDim.x + threadIdx.x;
    int nthr = blockDim.x * blockDim.y;

    for (int i = tid; i < CIN * COUT; i += nthr) Ws[i] = W[i];

    int nrows = min(ROWS, N - row0);
    for (int i = tid; i < nrows * CIN; i += nthr) Xs[i] = Xin[(size_t)row0 * CIN + i];
    __syncthreads();

    int c = threadIdx.x;
    for (int r = threadIdx.y; r < nrows; r += blockDim.y) {
        float acc = 0.f;
#pragma unroll
        for (int k = 0; k < CIN; k++) acc += Xs[r * CIN + k] * Ws[k * COUT + c];
        float o = acc;
        if (SCALE) o *= g_dinv[row0 + r];
        H[(size_t)(row0 + r) * COUT + c] = __float2half_rn(o);
    }
}

// ---------------------------------------------------------------------------
// Fused A: first half of gemm1 || degree histogram (4 edges/thread, int4).
// ---------------------------------------------------------------------------
__global__ void __launch_bounds__(256)
fusedA_kernel(const float* __restrict__ x, const float* __restrict__ W1,
              const int* __restrict__ ei, int E, int N, int GA, int DB) {
    if ((int)blockIdx.x < GA) {
        gemm_tile<C_IN, C_HID, false>(x, W1, g_h1h, N, blockIdx.x * 64);
    } else {
        int tid = threadIdx.y * blockDim.x + threadIdx.x;
        int bid = (int)blockIdx.x - GA;
        const int4* d4 = (const int4*)(ei + E);
        int nq = E >> 2;
        for (int q = bid * 256 + tid; q < nq; q += DB * 256) {
            int4 d = d4[q];
            atomicAdd(&g_deg[d.x], 1);
            atomicAdd(&g_deg[d.y], 1);
            atomicAdd(&g_deg[d.z], 1);
            atomicAdd(&g_deg[d.w], 1);
        }
        for (int e = (nq << 2) + bid * 256 + tid; e < E; e += DB * 256)
            atomicAdd(&g_deg[ei[E + e]], 1);
    }
}

// ---------------------------------------------------------------------------
// Scan-free CSR range allocation (proven R10/R12).
// ---------------------------------------------------------------------------
__global__ void __launch_bounds__(256)
alloc_kernel(int N) {
    __shared__ int warp_sums[8];
    __shared__ int s_base;
    int t    = threadIdx.x;
    int lane = t & 31;
    int wid  = t >> 5;
    int i0   = blockIdx.x * 512 + 2 * t;

    int a = (i0 < N)     ? g_deg[i0]     : 0;
    int b = (i0 + 1 < N) ? g_deg[i0 + 1] : 0;
    int pair = a + b;

    int v = pair;
#pragma unroll
    for (int o = 1; o < 32; o <<= 1) {
        int u = __shfl_up_sync(0xFFFFFFFFu, v, o);
        if (lane >= o) v += u;
    }
    if (lane == 31) warp_sums[wid] = v;
    __syncthreads();
    if (wid == 0) {
        int w = (lane < 8) ? warp_sums[lane] : 0;
#pragma unroll
        for (int o = 1; o < 32; o <<= 1) {
            int u = __shfl_up_sync(0xFFFFFFFFu, w, o);
            if (lane >= o) w += u;
        }
        if (lane < 8) warp_sums[lane] = w;
    }
    __syncthreads();
    int carry = (wid > 0) ? warp_sums[wid - 1] : 0;
    int incl  = v + carry;
    if (t == 255) s_base = atomicAdd(&g_total, incl);
    __syncthreads();
    int excl = incl - pair + s_base;
    if (i0 < N) {
        g_start[i0]  = excl;
        g_cursor[i0] = excl;
        g_dinv[i0]   = rsqrtf((float)(a + 1));
        g_deg[i0]    = 0;
    }
    if (i0 + 1 < N) {
        g_start[i0 + 1]  = excl + a;
        g_cursor[i0 + 1] = excl + a;
        g_dinv[i0 + 1]   = rsqrtf((float)(b + 1));
        g_deg[i0 + 1]    = 0;
    }
}

// ---------------------------------------------------------------------------
// Fused B: second half of gemm1 || CSR fill (4 edges/thread).
// ---------------------------------------------------------------------------
__global__ void __launch_bounds__(256)
fusedB_kernel(const float* __restrict__ x, const float* __restrict__ W1,
              const int* __restrict__ ei, int E, int N, int GA, int GB, int FB) {
    if ((int)blockIdx.x < GB) {
        gemm_tile<C_IN, C_HID, false>(x, W1, g_h1h, N, (GA + blockIdx.x) * 64);
    } else {
        int tid = threadIdx.y * blockDim.x + threadIdx.x;
        int bid = (int)blockIdx.x - GB;
        const int4* s4 = (const int4*)ei;
        const int4* d4 = (const int4*)(ei + E);
        int nq = E >> 2;
        for (int q = bid * 256 + tid; q < nq; q += FB * 256) {
            int4 s = s4[q];
            int4 d = d4[q];
            g_csr[atomicAdd(&g_cursor[d.x], 1)] = s.x;
            g_csr[atomicAdd(&g_cursor[d.y], 1)] = s.y;
            g_csr[atomicAdd(&g_cursor[d.z], 1)] = s.z;
            g_csr[atomicAdd(&g_cursor[d.w], 1)] = s.w;
        }
        for (int e = (nq << 2) + bid * 256 + tid; e < E; e += FB * 256) {
            int s = ei[e];
            int d = ei[E + e];
            g_csr[atomicAdd(&g_cursor[d], 1)] = s;
        }
    }
}

// ---------------------------------------------------------------------------
// Layer-1 aggregate (fp16 gathers, fp32 math):
//   feat[d] = relu(dinv[d]*(dinv[d]*h1[d] + sum_s dinv[s]*h1[s]) + b1)
// Half-warp per node; lane gathers 4 halves (8B); 4-way index-batched.
// ---------------------------------------------------------------------------
__global__ void __launch_bounds__(256)
agg1_kernel(const float* __restrict__ b1, int N) {
    int lane = threadIdx.x & 31;
    int warp = (blockIdx.x * blockDim.x + threadIdx.x) >> 5;
    int node = warp * 2 + (lane >> 4);
    if (node >= N) return;
    int sub = lane & 15;

    const uint2* hs = (const uint2*)g_h1h;  // row stride 16 uint2 (64 halves)
    float dn = g_dinv[node];

    float4 self = h4_to_f4(hs[node * 16 + sub]);
    float4 acc;
    acc.x = self.x * dn; acc.y = self.y * dn;
    acc.z = self.z * dn; acc.w = self.w * dn;

    int i = g_start[node], end = g_cursor[node];
    for (; i + 4 <= end; i += 4) {
        int s0 = g_csr[i], s1 = g_csr[i + 1], s2 = g_csr[i + 2], s3 = g_csr[i + 3];
        float d0 = g_dinv[s0], d1 = g_dinv[s1], d2 = g_dinv[s2], d3 = g_dinv[s3];
        float4 a0 = h4_to_f4(hs[s0 * 16 + sub]);
        float4 a1 = h4_to_f4(hs[s1 * 16 + sub]);
        float4 a2 = h4_to_f4(hs[s2 * 16 + sub]);
        float4 a3 = h4_to_f4(hs[s3 * 16 + sub]);
        acc.x = fmaf(a0.x, d0, fmaf(a1.x, d1, fmaf(a2.x, d2, fmaf(a3.x, d3, acc.x))));
        acc.y = fmaf(a0.y, d0, fmaf(a1.y, d1, fmaf(a2.y, d2, fmaf(a3.y, d3, acc.y))));
        acc.z = fmaf(a0.z, d0, fmaf(a1.z, d1, fmaf(a2.z, d2, fmaf(a3.z, d3, acc.z))));
        acc.w = fmaf(a0.w, d0, fmaf(a1.w, d1, fmaf(a2.w, d2, fmaf(a3.w, d3, acc.w))));
    }
    for (; i < end; i++) {
        int s = g_csr[i];
        float ds = g_dinv[s];
        float4 a = h4_to_f4(hs[s * 16 + sub]);
        acc.x = fmaf(a.x, ds, acc.x);
        acc.y = fmaf(a.y, ds, acc.y);
        acc.z = fmaf(a.z, ds, acc.z);
        acc.w = fmaf(a.w, ds, acc.w);
    }
    int c = sub * 4;
    float4 o;
    o.x = fmaxf(fmaf(acc.x, dn, b1[c + 0]), 0.f);
    o.y = fmaxf(fmaf(acc.y, dn, b1[c + 1]), 0.f);
    o.z = fmaxf(fmaf(acc.z, dn, b1[c + 2]), 0.f);
    o.w = fmaxf(fmaf(acc.w, dn, b1[c + 3]), 0.f);
    ((float4*)g_feat)[node * 16 + sub] = o;
}

// ---------------------------------------------------------------------------
// Layer 2 GEMM: h2h[r,:] = half((feat[r,:] @ W2) * dinv[r]).
// ---------------------------------------------------------------------------
__global__ void gemm2_kernel(const float* __restrict__ W, int N) {
    gemm_tile<C_HID, C_OUT, true>(g_feat, W, g_h2h, N, blockIdx.x * 64);
}

// ---------------------------------------------------------------------------
// Layer-2 aggregate + bias + log_softmax (fp16 gathers, fp32 math).
// Row = 40 halves = 10 uint2; lanes sub<10 carry data.
// Resets g_total for the next invocation.
// ---------------------------------------------------------------------------
__global__ void agg2_kernel(const float* __restrict__ b2,
                            float* __restrict__ out, int N) {
    if (blockIdx.x == 0 && threadIdx.x == 0) g_total = 0;

    int lane = threadIdx.x & 31;
    int warp = (blockIdx.x * blockDim.x + threadIdx.x) >> 5;
    int node = warp * 2 + (lane >> 4);
    int sub  = lane & 15;
    bool valid = (node < N) && (sub < 10);
    int nc = (node < N) ? node : 0;

    float4 v = make_float4(-INFINITY, -INFINITY, -INFINITY, -INFINITY);
    if (valid) {
        const uint2* hs = (const uint2*)g_h2h;  // row stride 10 uint2
        float4 acc = h4_to_f4(hs[nc * 10 + sub]);  // self loop
        int i = g_start[nc], end = g_cursor[nc];
        for (; i + 4 <= end; i += 4) {
            int s0 = g_csr[i], s1 = g_csr[i + 1], s2 = g_csr[i + 2], s3 = g_csr[i + 3];
            float4 a0 = h4_to_f4(hs[s0 * 10 + sub]);
            float4 a1 = h4_to_f4(hs[s1 * 10 + sub]);
            float4 a2 = h4_to_f4(hs[s2 * 10 + sub]);
            float4 a3 = h4_to_f4(hs[s3 * 10 + sub]);
            acc.x += (a0.x + a1.x) + (a2.x + a3.x);
            acc.y += (a0.y + a1.y) + (a2.y + a3.y);
            acc.z += (a0.z + a1.z) + (a2.z + a3.z);
            acc.w += (a0.w + a1.w) + (a2.w + a3.w);
        }
        for (; i < end; i++) {
            float4 a = h4_to_f4(hs[g_csr[i] * 10 + sub]);
            acc.x += a.x; acc.y += a.y; acc.z += a.z; acc.w += a.w;
        }
        float di = g_dinv[nc];
        int c = sub * 4;
        v = make_float4(fmaf(acc.x, di, b2[c + 0]),
                        fmaf(acc.y, di, b2[c + 1]),
                        fmaf(acc.z, di, b2[c + 2]),
                        fmaf(acc.w, di, b2[c + 3]));
    }

    float m = fmaxf(fmaxf(v.x, v.y), fmaxf(v.z, v.w));
#pragma unroll
    for (int o = 8; o; o >>= 1) m = fmaxf(m, __shfl_xor_sync(0xFFFFFFFFu, m, o));

    float s = valid ? (expf(v.x - m) + expf(v.y - m) + expf(v.z - m) + expf(v.w - m))
                    : 0.f;
#pragma unroll
    for (int o = 8; o; o >>= 1) s += __shfl_xor_sync(0xFFFFFFFFu, s, o);

    float lg = m + logf(s);
    if (valid) {
        float4 o4 = make_float4(v.x - lg, v.y - lg, v.z - lg, v.w - lg);
        ((float4*)out)[nc * 10 + sub] = o4;
    }
}

// ---------------------------------------------------------------------------
extern "C" void kernel_launch(void* const* d_in, const int* in_sizes, int n_in,
                              void* d_out, int out_size) {
    const float* x  = (const float*)d_in[0];
    const int*   ei = (const int*)d_in[1];
    const float* W1 = (const float*)d_in[2];
    const float* b1 = (const float*)d_in[3];
    const float* W2 = (const float*)d_in[4];
    const float* b2 = (const float*)d_in[5];
    float* out = (float*)d_out;

    int N = in_sizes[0] / C_IN;
    int E = in_sizes[1] / 2;

    int G  = (N + 63) / 64;   // gemm tiles
    int GA = (G + 1) / 2;
    int GB = G - GA;
    int DB = 512;             // deg partner blocks
    int FB = 512;             // fill partner blocks

    fusedA_kernel<<<GA + DB, dim3(64, 4)>>>(x, W1, ei, E, N, GA, DB);
    alloc_kernel<<<(N + 511) / 512, 256>>>(N);
    fusedB_kernel<<<GB + FB, dim3(64, 4)>>>(x, W1, ei, E, N, GA, GB, FB);
    agg1_kernel<<<(N + 15) / 16, 256>>>(b1, N);
    gemm2_kernel<<<G, dim3(C_OUT, 6)>>>(W2, N);
    agg2_kernel<<<(N + 15) / 16, 256>>>(b2, out, N);
}